// round 1
// baseline (speedup 1.0000x reference)
#include <cuda_runtime.h>
#include <cuda_bf16.h>

#define SEQ   512
#define BATCH 2048
#define NTOK  (SEQ * BATCH)

// ping-pong intermediate buffers [S, B, 16] fp32 (64 MB each)
__device__ float g_bufA[(size_t)NTOK * 16];
__device__ float g_bufB[(size_t)NTOK * 16];

__device__ __forceinline__ float sigf(float x) {
    return 1.0f / (1.0f + __expf(-x));
}
__device__ __forceinline__ float tanh_fast(float x) {
    // 2/(1+exp(-2x)) - 1 ; saturates correctly at +-1
    return 2.0f / (1.0f + __expf(-2.0f * x)) - 1.0f;
}

// ---------------------------------------------------------------------------
// Kernel 1: embedding lookup + h = emb @ w_e.T + b_e   -> g_bufA [S,B,16]
// 16 lanes per token, lane ch computes output channel ch.
// ---------------------------------------------------------------------------
__global__ void embed_kernel(const int* __restrict__ x,
                             const float* __restrict__ table,
                             const float* __restrict__ w_e,
                             const float* __restrict__ b_e) {
    int tid = blockIdx.x * blockDim.x + threadIdx.x;
    int ch = tid & 15;
    int g  = tid >> 4;
    int G  = (gridDim.x * blockDim.x) >> 4;

    float w[16];
#pragma unroll
    for (int k = 0; k < 16; k++) w[k] = w_e[ch * 16 + k];
    float bb = b_e[ch];

    for (int tok = g; tok < NTOK; tok += G) {
        int vid = x[tok];
        const float4* er = reinterpret_cast<const float4*>(table + (size_t)vid * 16);
        float4 e0 = er[0], e1 = er[1], e2 = er[2], e3 = er[3];
        float ev[16] = {e0.x, e0.y, e0.z, e0.w, e1.x, e1.y, e1.z, e1.w,
                        e2.x, e2.y, e2.z, e2.w, e3.x, e3.y, e3.z, e3.w};
        float acc = bb;
#pragma unroll
        for (int k = 0; k < 16; k++) acc = fmaf(w[k], ev[k], acc);
        g_bufA[(size_t)tok * 16 + ch] = acc;
    }
}

// ---------------------------------------------------------------------------
// Kernel 2: one bidirectional GRU layer. blockIdx.y = direction (0=fwd,1=bwd).
// 8 threads per batch element; lane j owns hidden unit j. All weights in
// registers; h broadcast via width-8 shuffles. gi computed on the fly.
// flip=0: in=g_bufA out=g_bufB ; flip=1: in=g_bufB out=g_bufA
// ---------------------------------------------------------------------------
__global__ void __launch_bounds__(256) gru_kernel(
        const float* __restrict__ wih_all,
        const float* __restrict__ whh_all,
        const float* __restrict__ bih_all,
        const float* __restrict__ bhh_all,
        int layer, int flip) {
    const float* __restrict__ in  = flip ? g_bufB : g_bufA;
    float* __restrict__       out = flip ? g_bufA : g_bufB;

    const int d = blockIdx.y;                       // direction
    const int j = threadIdx.x & 7;                  // hidden unit
    const int b = blockIdx.x * 32 + (threadIdx.x >> 3);

    const int w = layer * 2 + d;
    const float* wih = wih_all + (size_t)w * 24 * 16;
    const float* whh = whh_all + (size_t)w * 24 * 8;
    const float* bih = bih_all + (size_t)w * 24;
    const float* bhh = bhh_all + (size_t)w * 24;

    float wir[16], wiz[16], win[16];
#pragma unroll
    for (int k = 0; k < 16; k++) {
        wir[k] = wih[(0  + j) * 16 + k];
        wiz[k] = wih[(8  + j) * 16 + k];
        win[k] = wih[(16 + j) * 16 + k];
    }
    float whr[8], whz[8], whn[8];
#pragma unroll
    for (int k = 0; k < 8; k++) {
        whr[k] = whh[(0  + j) * 8 + k];
        whz[k] = whh[(8  + j) * 8 + k];
        whn[k] = whh[(16 + j) * 8 + k];
    }
    const float br   = bih[j]      + bhh[j];
    const float bz   = bih[8 + j]  + bhh[8 + j];
    const float bn_i = bih[16 + j];
    const float bn_h = bhh[16 + j];

    float h = 0.0f;
    int t  = d ? (SEQ - 1) : 0;
    const int dt = d ? -1 : 1;
    const int oc = d * 8 + j;

    for (int s = 0; s < SEQ; s++, t += dt) {
        const float4* xp = reinterpret_cast<const float4*>(
            in + ((size_t)t * BATCH + b) * 16);
        float4 a0 = xp[0], a1 = xp[1], a2 = xp[2], a3 = xp[3];
        float xv[16] = {a0.x, a0.y, a0.z, a0.w, a1.x, a1.y, a1.z, a1.w,
                        a2.x, a2.y, a2.z, a2.w, a3.x, a3.y, a3.z, a3.w};
        float gr = br, gz = bz, gn = bn_i;
#pragma unroll
        for (int k = 0; k < 16; k++) {
            gr = fmaf(wir[k], xv[k], gr);
            gz = fmaf(wiz[k], xv[k], gz);
            gn = fmaf(win[k], xv[k], gn);
        }
        float ghr = 0.0f, ghz = 0.0f, ghn = bn_h;
#pragma unroll
        for (int k = 0; k < 8; k++) {
            float hk = __shfl_sync(0xffffffffu, h, k, 8);
            ghr = fmaf(whr[k], hk, ghr);
            ghz = fmaf(whz[k], hk, ghz);
            ghn = fmaf(whn[k], hk, ghn);
        }
        float r = sigf(gr + ghr);
        float z = sigf(gz + ghz);
        float n = tanh_fast(fmaf(r, ghn, gn));
        h = fmaf(z, h - n, n);                      // (1-z)*n + z*h
        out[((size_t)t * BATCH + b) * 16 + oc] = h;
    }
}

// ---------------------------------------------------------------------------
// Kernel 3: head: out = gelu(h @ w_g.T + b_g) @ w_o.T + b_o  (exact gelu)
// 16 lanes/token: lane ch computes y_ch, then lanes 0..9 reduce over y via
// width-16 shuffles. Reads g_bufA (result of layer 1).
// ---------------------------------------------------------------------------
__global__ void head_kernel(const float* __restrict__ w_g,
                            const float* __restrict__ b_g,
                            const float* __restrict__ w_o,
                            const float* __restrict__ b_o,
                            float* __restrict__ out) {
    int tid = blockIdx.x * blockDim.x + threadIdx.x;
    int ch = tid & 15;
    int g  = tid >> 4;
    int G  = (gridDim.x * blockDim.x) >> 4;

    float wg[16];
#pragma unroll
    for (int k = 0; k < 16; k++) wg[k] = w_g[ch * 16 + k];
    float bg = b_g[ch];

    float wo[16];
    float bo = 0.0f;
    if (ch < 10) {
#pragma unroll
        for (int k = 0; k < 16; k++) wo[k] = w_o[ch * 16 + k];
        bo = b_o[ch];
    } else {
#pragma unroll
        for (int k = 0; k < 16; k++) wo[k] = 0.0f;
    }

    for (int tok = g; tok < NTOK; tok += G) {
        const float4* hp = reinterpret_cast<const float4*>(g_bufA + (size_t)tok * 16);
        float4 a0 = hp[0], a1 = hp[1], a2 = hp[2], a3 = hp[3];
        float hv[16] = {a0.x, a0.y, a0.z, a0.w, a1.x, a1.y, a1.z, a1.w,
                        a2.x, a2.y, a2.z, a2.w, a3.x, a3.y, a3.z, a3.w};
        float acc = bg;
#pragma unroll
        for (int k = 0; k < 16; k++) acc = fmaf(wg[k], hv[k], acc);
        float y = acc * normcdff(acc);              // exact gelu
        float o = bo;
#pragma unroll
        for (int k = 0; k < 16; k++) {
            float yk = __shfl_sync(0xffffffffu, y, k, 16);
            o = fmaf(wo[k], yk, o);
        }
        if (ch < 10) out[(size_t)tok * 10 + ch] = o;
    }
}

// ---------------------------------------------------------------------------
extern "C" void kernel_launch(void* const* d_in, const int* in_sizes, int n_in,
                              void* d_out, int out_size) {
    const int*   x     = (const int*)d_in[0];
    const float* table = (const float*)d_in[1];
    const float* w_e   = (const float*)d_in[2];
    const float* b_e   = (const float*)d_in[3];
    const float* wih   = (const float*)d_in[4];
    const float* whh   = (const float*)d_in[5];
    const float* bih   = (const float*)d_in[6];
    const float* bhh   = (const float*)d_in[7];
    const float* w_g   = (const float*)d_in[8];
    const float* b_g   = (const float*)d_in[9];
    const float* w_o   = (const float*)d_in[10];
    const float* b_o   = (const float*)d_in[11];
    float* out = (float*)d_out;

    embed_kernel<<<8192, 256>>>(x, table, w_e, b_e);        // -> g_bufA

    dim3 gg(BATCH / 32, 2);
    gru_kernel<<<gg, 256>>>(wih, whh, bih, bhh, 0, 0);      // A -> B
    gru_kernel<<<gg, 256>>>(wih, whh, bih, bhh, 1, 1);      // B -> A

    head_kernel<<<8192, 256>>>(w_g, b_g, w_o, b_o, out);    // A -> out
}

// round 2
// speedup vs baseline: 1.6427x; 1.6427x over previous
#include <cuda_runtime.h>
#include <cuda_bf16.h>

#define SEQ   512
#define BATCH 2048
#define NTOK  (SEQ * BATCH)
#define VOCAB 50000

// scratch ( __device__ globals: allocation-free )
__device__ float g_M0[48 * 16];                 // fused wih0 @ w_e
__device__ float g_c0[48];                      // fused bias
__device__ float g_G0[(size_t)VOCAB * 48];      // per-vocab layer0 input gates (9.6MB, L2)
__device__ float g_h0[(size_t)NTOK * 16];       // layer0 output
#define GI1_PAD ((size_t)2 * BATCH * 48)        // 2-step prefetch overrun pad each side
__device__ float g_gi1_raw[GI1_PAD + (size_t)NTOK * 48 + GI1_PAD];
__device__ float g_h1[(size_t)NTOK * 16];       // layer1 output

__device__ __forceinline__ float sigf(float x) {
    return 1.0f / (1.0f + __expf(-x));
}
__device__ __forceinline__ float tanh_fast(float x) {
    return 2.0f / (1.0f + __expf(-2.0f * x)) - 1.0f;
}

// ---------------------------------------------------------------------------
// prep: M0[o][e] = sum_h wih0[o][h] * w_e[h][e] ; c0[o] = bih0[o] + wih0[o]·b_e
// (o = d*24 + row, flat over layer-0's [2][24] rows)
// ---------------------------------------------------------------------------
__global__ void prep_M0(const float* __restrict__ w_e, const float* __restrict__ b_e,
                        const float* __restrict__ wih, const float* __restrict__ bih) {
    int tid = threadIdx.x;
    if (tid < 768) {
        int o = tid >> 4, e = tid & 15;
        float acc = 0.0f;
#pragma unroll
        for (int h = 0; h < 16; h++) acc = fmaf(wih[o * 16 + h], w_e[h * 16 + e], acc);
        g_M0[o * 16 + e] = acc;
    }
    if (tid < 48) {
        float acc = bih[tid];
#pragma unroll
        for (int h = 0; h < 16; h++) acc = fmaf(wih[tid * 16 + h], b_e[h], acc);
        g_c0[tid] = acc;
    }
}

// G0[v][o] = table[v]·M0[o] + c0[o]
__global__ void build_G0(const float* __restrict__ table) {
    int idx = blockIdx.x * blockDim.x + threadIdx.x;
    if (idx >= VOCAB * 48) return;
    int v = idx / 48, o = idx - v * 48;
    const float* tr = table + (size_t)v * 16;
    const float* mr = g_M0 + o * 16;
    float acc = g_c0[o];
#pragma unroll
    for (int e = 0; e < 16; e++) acc = fmaf(tr[e], mr[e], acc);
    g_G0[idx] = acc;
}

// ---------------------------------------------------------------------------
// scan0: layer-0 GRU. 8 threads/batch element, lane j owns h_j.
// Input gates gathered straight from G0 via the token id (L2-resident),
// prefetched 2 steps ahead (vocab ids 4 steps ahead).
// ---------------------------------------------------------------------------
__global__ void __launch_bounds__(64) scan0_kernel(
        const int* __restrict__ x,
        const float* __restrict__ whh_all,
        const float* __restrict__ bhh_all) {
    const int d = blockIdx.y;
    const int j = threadIdx.x & 7;
    const int b = blockIdx.x * 8 + (threadIdx.x >> 3);

    const float* whh = whh_all + d * 24 * 8;      // layer 0
    const float* bhh = bhh_all + d * 24;

    float whr[8], whz[8], whn[8];
#pragma unroll
    for (int k = 0; k < 8; k++) {
        whr[k] = whh[(0  + j) * 8 + k];
        whz[k] = whh[(8  + j) * 8 + k];
        whn[k] = whh[(16 + j) * 8 + k];
    }
    const float br = bhh[j], bz = bhh[8 + j], bn = bhh[16 + j];
    const int go = d * 24 + j;

    auto tmap = [&](int s) {                       // clamped, direction-mapped time
        int c = s < SEQ - 1 ? s : SEQ - 1;
        return d ? (SEQ - 1 - c) : c;
    };

    int vid2 = x[(size_t)tmap(2) * BATCH + b];
    int vid3 = x[(size_t)tmap(3) * BATCH + b];
    float gr0, gz0, gn0, gr1, gz1, gn1;
    {
        int v0 = x[(size_t)tmap(0) * BATCH + b];
        int v1 = x[(size_t)tmap(1) * BATCH + b];
        const float* r0 = g_G0 + (size_t)v0 * 48 + go;
        gr0 = r0[0]; gz0 = r0[8]; gn0 = r0[16];
        const float* r1 = g_G0 + (size_t)v1 * 48 + go;
        gr1 = r1[0]; gz1 = r1[8]; gn1 = r1[16];
    }

    float h = 0.0f;
    for (int s = 0; s < SEQ; s++) {
        // prefetch (clamped tail reads are valid memory, values unused)
        int vid4 = x[(size_t)tmap(s + 4) * BATCH + b];
        const float* r2 = g_G0 + (size_t)vid2 * 48 + go;
        float gr2 = r2[0], gz2 = r2[8], gn2 = r2[16];

        float ghr = br, ghz = bz, ghn = bn;
#pragma unroll
        for (int k = 0; k < 8; k++) {
            float hk = __shfl_sync(0xffffffffu, h, k, 8);
            ghr = fmaf(whr[k], hk, ghr);
            ghz = fmaf(whz[k], hk, ghz);
            ghn = fmaf(whn[k], hk, ghn);
        }
        float r = sigf(gr0 + ghr);
        float z = sigf(gz0 + ghz);
        float n = tanh_fast(fmaf(r, ghn, gn0));
        h = fmaf(z, h - n, n);

        int tt = d ? (SEQ - 1 - s) : s;
        g_h0[((size_t)tt * BATCH + b) * 16 + d * 8 + j] = h;

        gr0 = gr1; gz0 = gz1; gn0 = gn1;
        gr1 = gr2; gz1 = gz2; gn1 = gn2;
        vid2 = vid3; vid3 = vid4;
    }
}

// ---------------------------------------------------------------------------
// gi1: gi1[tok][o] = h0[tok]·wih1[o] + bih1[o].  16 lanes/token (2 tokens/warp),
// one coalesced float load per lane, h broadcast via width-16 shuffles,
// weights (3x16 per lane) in registers, grid-stride to amortize weight loads.
// ---------------------------------------------------------------------------
__global__ void __launch_bounds__(256) gi1_kernel(
        const float* __restrict__ wih_all, const float* __restrict__ bih_all) {
    int gtid = blockIdx.x * blockDim.x + threadIdx.x;
    int L = gtid & 15;
    int slot = gtid >> 4;
    int G = (gridDim.x * blockDim.x) >> 4;

    const float* wbase = wih_all + 48 * 16;        // layer 1
    float w0[16], w1[16], w2[16];
#pragma unroll
    for (int k = 0; k < 16; k++) {
        w0[k] = wbase[(L     ) * 16 + k];
        w1[k] = wbase[(L + 16) * 16 + k];
        w2[k] = wbase[(L + 32) * 16 + k];
    }
    const float c0 = bih_all[48 + L];
    const float c1 = bih_all[48 + L + 16];
    const float c2 = bih_all[48 + L + 32];

    float* gi1 = g_gi1_raw + GI1_PAD;
    for (int tok = slot; tok < NTOK; tok += G) {
        float hv = g_h0[(size_t)tok * 16 + L];
        float a0 = c0, a1 = c1, a2 = c2;
#pragma unroll
        for (int k = 0; k < 16; k++) {
            float hk = __shfl_sync(0xffffffffu, hv, k, 16);
            a0 = fmaf(w0[k], hk, a0);
            a1 = fmaf(w1[k], hk, a1);
            a2 = fmaf(w2[k], hk, a2);
        }
        size_t ob = (size_t)tok * 48;
        gi1[ob + L] = a0;
        gi1[ob + 16 + L] = a1;
        gi1[ob + 32 + L] = a2;
    }
}

// ---------------------------------------------------------------------------
// scan1: layer-1 GRU, input gates read linearly from gi1 (pointer-walk,
// 2-step prefetch into the pad region at the ends).
// ---------------------------------------------------------------------------
__global__ void __launch_bounds__(64) scan1_kernel(
        const float* __restrict__ whh_all,
        const float* __restrict__ bhh_all) {
    const int d = blockIdx.y;
    const int j = threadIdx.x & 7;
    const int b = blockIdx.x * 8 + (threadIdx.x >> 3);

    const float* whh = whh_all + (2 + d) * 24 * 8;   // layer 1
    const float* bhh = bhh_all + (2 + d) * 24;

    float whr[8], whz[8], whn[8];
#pragma unroll
    for (int k = 0; k < 8; k++) {
        whr[k] = whh[(0  + j) * 8 + k];
        whz[k] = whh[(8  + j) * 8 + k];
        whn[k] = whh[(16 + j) * 8 + k];
    }
    const float br = bhh[j], bz = bhh[8 + j], bn = bhh[16 + j];

    const int t0 = d ? (SEQ - 1) : 0;
    const ptrdiff_t step = (d ? -1 : 1) * (ptrdiff_t)BATCH * 48;
    const float* p = g_gi1_raw + GI1_PAD +
                     ((size_t)t0 * BATCH + b) * 48 + d * 24 + j;

    float gr0 = p[0],        gz0 = p[8],        gn0 = p[16];
    float gr1 = p[step],     gz1 = p[step + 8], gn1 = p[step + 16];
    const float* pf = p + 2 * step;               // prefetch pointer

    float h = 0.0f;
    int t = t0;
    const int dt = d ? -1 : 1;
    for (int s = 0; s < SEQ; s++, t += dt) {
        float gr2 = pf[0], gz2 = pf[8], gn2 = pf[16];
        pf += step;                                // runs 2 steps into pad at tail

        float ghr = br, ghz = bz, ghn = bn;
#pragma unroll
        for (int k = 0; k < 8; k++) {
            float hk = __shfl_sync(0xffffffffu, h, k, 8);
            ghr = fmaf(whr[k], hk, ghr);
            ghz = fmaf(whz[k], hk, ghz);
            ghn = fmaf(whn[k], hk, ghn);
        }
        float r = sigf(gr0 + ghr);
        float z = sigf(gz0 + ghz);
        float n = tanh_fast(fmaf(r, ghn, gn0));
        h = fmaf(z, h - n, n);

        g_h1[((size_t)t * BATCH + b) * 16 + d * 8 + j] = h;

        gr0 = gr1; gz0 = gz1; gn0 = gn1;
        gr1 = gr2; gz1 = gz2; gn1 = gn2;
    }
}

// ---------------------------------------------------------------------------
// head: out = gelu(h1 @ w_g.T + b_g) @ w_o.T + b_o.  16 lanes/token,
// one coalesced load per lane + shuffle broadcast (no redundant L1 traffic).
// ---------------------------------------------------------------------------
__global__ void __launch_bounds__(256) head_kernel(
        const float* __restrict__ w_g, const float* __restrict__ b_g,
        const float* __restrict__ w_o, const float* __restrict__ b_o,
        float* __restrict__ out) {
    int gtid = blockIdx.x * blockDim.x + threadIdx.x;
    int L = gtid & 15;
    int slot = gtid >> 4;
    int G = (gridDim.x * blockDim.x) >> 4;

    float wg[16];
#pragma unroll
    for (int k = 0; k < 16; k++) wg[k] = w_g[L * 16 + k];
    float bg = b_g[L];

    float wo[16];
    float bo = 0.0f;
    if (L < 10) {
#pragma unroll
        for (int k = 0; k < 16; k++) wo[k] = w_o[L * 16 + k];
        bo = b_o[L];
    } else {
#pragma unroll
        for (int k = 0; k < 16; k++) wo[k] = 0.0f;
    }

    for (int tok = slot; tok < NTOK; tok += G) {
        float hv = g_h1[(size_t)tok * 16 + L];
        float acc = bg;
#pragma unroll
        for (int k = 0; k < 16; k++)
            acc = fmaf(wg[k], __shfl_sync(0xffffffffu, hv, k, 16), acc);
        float y = acc * normcdff(acc);             // exact gelu
        float o = bo;
#pragma unroll
        for (int k = 0; k < 16; k++)
            o = fmaf(wo[k], __shfl_sync(0xffffffffu, y, k, 16), o);
        if (L < 10) out[(size_t)tok * 10 + L] = o;
    }
}

// ---------------------------------------------------------------------------
extern "C" void kernel_launch(void* const* d_in, const int* in_sizes, int n_in,
                              void* d_out, int out_size) {
    const int*   x     = (const int*)d_in[0];
    const float* table = (const float*)d_in[1];
    const float* w_e   = (const float*)d_in[2];
    const float* b_e   = (const float*)d_in[3];
    const float* wih   = (const float*)d_in[4];
    const float* whh   = (const float*)d_in[5];
    const float* bih   = (const float*)d_in[6];
    const float* bhh   = (const float*)d_in[7];
    const float* w_g   = (const float*)d_in[8];
    const float* b_g   = (const float*)d_in[9];
    const float* w_o   = (const float*)d_in[10];
    const float* b_o   = (const float*)d_in[11];
    float* out = (float*)d_out;

    prep_M0<<<1, 768>>>(w_e, b_e, wih, bih);
    build_G0<<<(VOCAB * 48 + 255) / 256, 256>>>(table);

    dim3 gs(BATCH / 8, 2);
    scan0_kernel<<<gs, 64>>>(x, whh, bhh);
    gi1_kernel<<<2048, 256>>>(wih, bih);
    scan1_kernel<<<gs, 64>>>(whh, bhh);
    head_kernel<<<2048, 256>>>(w_g, b_g, w_o, b_o, out);
}

// round 3
// speedup vs baseline: 1.6626x; 1.0121x over previous
#include <cuda_runtime.h>
#include <cuda_bf16.h>

#define SEQ   512
#define BATCH 2048
#define NTOK  (SEQ * BATCH)
#define VOCAB 50000

// scratch ( __device__ globals: allocation-free )
__device__ float g_M0[48 * 16];                 // fused wih0 @ w_e
__device__ float g_c0[48];                      // fused bias
__device__ float g_G0[(size_t)VOCAB * 48];      // per-vocab layer0 input gates (9.6MB, L2)
#define H0PAD ((size_t)2 * BATCH * 16)          // 2-step prefetch overrun pad each side
__device__ float g_h0_raw[H0PAD + (size_t)NTOK * 16 + H0PAD];
__device__ float g_h1[(size_t)NTOK * 16];       // layer1 output

__device__ __forceinline__ float tanhap(float x) {
    float y;
    asm("tanh.approx.f32 %0, %1;" : "=f"(y) : "f"(x));
    return y;
}
__device__ __forceinline__ float sigap(float x) {
    return fmaf(0.5f, tanhap(0.5f * x), 0.5f);
}

// ---------------------------------------------------------------------------
// prep: M0[o][e] = sum_h wih0[o][h] * w_e[h][e] ; c0[o] = bih0[o] + wih0[o]·b_e
// ---------------------------------------------------------------------------
__global__ void prep_M0(const float* __restrict__ w_e, const float* __restrict__ b_e,
                        const float* __restrict__ wih, const float* __restrict__ bih) {
    int tid = threadIdx.x;
    if (tid < 768) {
        int o = tid >> 4, e = tid & 15;
        float acc = 0.0f;
#pragma unroll
        for (int h = 0; h < 16; h++) acc = fmaf(wih[o * 16 + h], w_e[h * 16 + e], acc);
        g_M0[o * 16 + e] = acc;
    }
    if (tid < 48) {
        float acc = bih[tid];
#pragma unroll
        for (int h = 0; h < 16; h++) acc = fmaf(wih[tid * 16 + h], b_e[h], acc);
        g_c0[tid] = acc;
    }
}

// G0[v][o] = table[v]·M0[o] + c0[o]
__global__ void build_G0(const float* __restrict__ table) {
    int idx = blockIdx.x * blockDim.x + threadIdx.x;
    if (idx >= VOCAB * 48) return;
    int v = idx / 48, o = idx - v * 48;
    const float* tr = table + (size_t)v * 16;
    const float* mr = g_M0 + o * 16;
    float acc = g_c0[o];
#pragma unroll
    for (int e = 0; e < 16; e++) acc = fmaf(tr[e], mr[e], acc);
    g_G0[idx] = acc;
}

// ---------------------------------------------------------------------------
// scan0: layer-0 GRU. 8 threads/batch element, lane j owns h_j.
// Input gates gathered straight from G0 via the token id (L2-resident),
// prefetched 2 steps ahead (vocab ids 4 steps ahead).
// ---------------------------------------------------------------------------
__global__ void __launch_bounds__(64) scan0_kernel(
        const int* __restrict__ x,
        const float* __restrict__ whh_all,
        const float* __restrict__ bhh_all) {
    const int d = blockIdx.y;
    const int j = threadIdx.x & 7;
    const int b = blockIdx.x * 8 + (threadIdx.x >> 3);

    const float* whh = whh_all + d * 24 * 8;      // layer 0
    const float* bhh = bhh_all + d * 24;

    float whr[8], whz[8], whn[8];
#pragma unroll
    for (int k = 0; k < 8; k++) {
        whr[k] = whh[(0  + j) * 8 + k];
        whz[k] = whh[(8  + j) * 8 + k];
        whn[k] = whh[(16 + j) * 8 + k];
    }
    const float br = bhh[j], bz = bhh[8 + j], bn = bhh[16 + j];
    const int go = d * 24 + j;

    auto tmap = [&](int s) {                       // clamped, direction-mapped time
        int c = s < SEQ - 1 ? s : SEQ - 1;
        return d ? (SEQ - 1 - c) : c;
    };

    int vid2 = x[(size_t)tmap(2) * BATCH + b];
    int vid3 = x[(size_t)tmap(3) * BATCH + b];
    float gr0, gz0, gn0, gr1, gz1, gn1;
    {
        int v0 = x[(size_t)tmap(0) * BATCH + b];
        int v1 = x[(size_t)tmap(1) * BATCH + b];
        const float* r0 = g_G0 + (size_t)v0 * 48 + go;
        gr0 = r0[0]; gz0 = r0[8]; gn0 = r0[16];
        const float* r1 = g_G0 + (size_t)v1 * 48 + go;
        gr1 = r1[0]; gz1 = r1[8]; gn1 = r1[16];
    }

    float* h0 = g_h0_raw + H0PAD;
    float h = 0.0f;
    for (int s = 0; s < SEQ; s++) {
        int vid4 = x[(size_t)tmap(s + 4) * BATCH + b];
        const float* r2 = g_G0 + (size_t)vid2 * 48 + go;
        float gr2 = r2[0], gz2 = r2[8], gn2 = r2[16];

        float ghr = br, ghz = bz, ghn = bn;
#pragma unroll
        for (int k = 0; k < 8; k++) {
            float hk = __shfl_sync(0xffffffffu, h, k, 8);
            ghr = fmaf(whr[k], hk, ghr);
            ghz = fmaf(whz[k], hk, ghz);
            ghn = fmaf(whn[k], hk, ghn);
        }
        float r = sigap(gr0 + ghr);
        float z = sigap(gz0 + ghz);
        float n = tanhap(fmaf(r, ghn, gn0));
        h = fmaf(z, h - n, n);

        int tt = d ? (SEQ - 1 - s) : s;
        h0[((size_t)tt * BATCH + b) * 16 + d * 8 + j] = h;

        gr0 = gr1; gz0 = gz1; gn0 = gn1;
        gr1 = gr2; gz1 = gz2; gn1 = gn2;
        vid2 = vid3; vid3 = vid4;
    }
}

// ---------------------------------------------------------------------------
// scan1: layer-1 GRU with the input-side matvec fused in (no gi1 buffer).
// 8 threads/(b,d); each step loads h0[t][b][2j..2j+1] (coalesced float2,
// prefetched 2 steps ahead), broadcasts via shuffles, and computes
// gi rows {j, j+8, j+16} on the fly (independent of the serial h chain).
// ---------------------------------------------------------------------------
__global__ void __launch_bounds__(64) scan1_kernel(
        const float* __restrict__ wih_all,
        const float* __restrict__ bih_all,
        const float* __restrict__ whh_all,
        const float* __restrict__ bhh_all) {
    const int d = blockIdx.y;
    const int j = threadIdx.x & 7;
    const int b = blockIdx.x * 8 + (threadIdx.x >> 3);

    // layer-1 weights, this direction (rows local to the 24-row block)
    const float* wih = wih_all + (48 + d * 24) * 16;
    const float* bih = bih_all + 48 + d * 24;
    const float* whh = whh_all + (2 + d) * 24 * 8;
    const float* bhh = bhh_all + (2 + d) * 24;

    float air[16], aiz[16], ain[16];
#pragma unroll
    for (int k = 0; k < 16; k++) {
        air[k] = wih[(0  + j) * 16 + k];
        aiz[k] = wih[(8  + j) * 16 + k];
        ain[k] = wih[(16 + j) * 16 + k];
    }
    float whr[8], whz[8], whn[8];
#pragma unroll
    for (int k = 0; k < 8; k++) {
        whr[k] = whh[(0  + j) * 8 + k];
        whz[k] = whh[(8  + j) * 8 + k];
        whn[k] = whh[(16 + j) * 8 + k];
    }
    const float br = bih[j]      + bhh[j];
    const float bz = bih[8 + j]  + bhh[8 + j];
    const float bni = bih[16 + j];
    const float bnh = bhh[16 + j];

    const int t0 = d ? (SEQ - 1) : 0;
    const int dt = d ? -1 : 1;
    const ptrdiff_t stp = (ptrdiff_t)dt * BATCH * 8;    // in float2 units

    const float2* p = reinterpret_cast<const float2*>(
        g_h0_raw + H0PAD + ((size_t)t0 * BATCH + b) * 16) + j;
    float2 x0 = p[0];
    float2 x1 = p[stp];
    const float2* pf = p + 2 * stp;                     // overruns into pad at tail

    float h = 0.0f;
    int t = t0;
    for (int s = 0; s < SEQ; s++, t += dt) {
        float2 x2 = *pf;
        pf += stp;

        // input-side gates (independent of h chain — fills its latency shadow)
        float gr = br, gz = bz, gn = bni;
#pragma unroll
        for (int k = 0; k < 8; k++) {
            float e0 = __shfl_sync(0xffffffffu, x0.x, k, 8);
            float e1 = __shfl_sync(0xffffffffu, x0.y, k, 8);
            gr = fmaf(air[2 * k], e0, gr); gr = fmaf(air[2 * k + 1], e1, gr);
            gz = fmaf(aiz[2 * k], e0, gz); gz = fmaf(aiz[2 * k + 1], e1, gz);
            gn = fmaf(ain[2 * k], e0, gn); gn = fmaf(ain[2 * k + 1], e1, gn);
        }

        // hidden-side gates (serial chain)
        float ghr = 0.0f, ghz = 0.0f, ghn = bnh;
#pragma unroll
        for (int k = 0; k < 8; k++) {
            float hk = __shfl_sync(0xffffffffu, h, k, 8);
            ghr = fmaf(whr[k], hk, ghr);
            ghz = fmaf(whz[k], hk, ghz);
            ghn = fmaf(whn[k], hk, ghn);
        }
        float r = sigap(gr + ghr);
        float z = sigap(gz + ghz);
        float n = tanhap(fmaf(r, ghn, gn));
        h = fmaf(z, h - n, n);

        g_h1[((size_t)t * BATCH + b) * 16 + d * 8 + j] = h;

        x0 = x1; x1 = x2;
    }
}

// ---------------------------------------------------------------------------
// head: out = gelu(h1 @ w_g.T + b_g) @ w_o.T + b_o.  16 lanes/token,
// one coalesced load per lane + shuffle broadcast.
// ---------------------------------------------------------------------------
__global__ void __launch_bounds__(256) head_kernel(
        const float* __restrict__ w_g, const float* __restrict__ b_g,
        const float* __restrict__ w_o, const float* __restrict__ b_o,
        float* __restrict__ out) {
    int gtid = blockIdx.x * blockDim.x + threadIdx.x;
    int L = gtid & 15;
    int slot = gtid >> 4;
    int G = (gridDim.x * blockDim.x) >> 4;

    float wg[16];
#pragma unroll
    for (int k = 0; k < 16; k++) wg[k] = w_g[L * 16 + k];
    float bg = b_g[L];

    float wo[16];
    float bo = 0.0f;
    if (L < 10) {
#pragma unroll
        for (int k = 0; k < 16; k++) wo[k] = w_o[L * 16 + k];
        bo = b_o[L];
    } else {
#pragma unroll
        for (int k = 0; k < 16; k++) wo[k] = 0.0f;
    }

    for (int tok = slot; tok < NTOK; tok += G) {
        float hv = g_h1[(size_t)tok * 16 + L];
        float acc = bg;
#pragma unroll
        for (int k = 0; k < 16; k++)
            acc = fmaf(wg[k], __shfl_sync(0xffffffffu, hv, k, 16), acc);
        float y = acc * normcdff(acc);             // exact gelu
        float o = bo;
#pragma unroll
        for (int k = 0; k < 16; k++)
            o = fmaf(wo[k], __shfl_sync(0xffffffffu, y, k, 16), o);
        if (L < 10) out[(size_t)tok * 10 + L] = o;
    }
}

// ---------------------------------------------------------------------------
extern "C" void kernel_launch(void* const* d_in, const int* in_sizes, int n_in,
                              void* d_out, int out_size) {
    const int*   x     = (const int*)d_in[0];
    const float* table = (const float*)d_in[1];
    const float* w_e   = (const float*)d_in[2];
    const float* b_e   = (const float*)d_in[3];
    const float* wih   = (const float*)d_in[4];
    const float* whh   = (const float*)d_in[5];
    const float* bih   = (const float*)d_in[6];
    const float* bhh   = (const float*)d_in[7];
    const float* w_g   = (const float*)d_in[8];
    const float* b_g   = (const float*)d_in[9];
    const float* w_o   = (const float*)d_in[10];
    const float* b_o   = (const float*)d_in[11];
    float* out = (float*)d_out;

    prep_M0<<<1, 768>>>(w_e, b_e, wih, bih);
    build_G0<<<(VOCAB * 48 + 255) / 256, 256>>>(table);

    dim3 gs(BATCH / 8, 2);
    scan0_kernel<<<gs, 64>>>(x, whh, bhh);
    scan1_kernel<<<gs, 64>>>(wih, bih, whh, bhh);
    head_kernel<<<2048, 256>>>(w_g, b_g, w_o, b_o, out);
}

// round 4
// speedup vs baseline: 1.8579x; 1.1175x over previous
#include <cuda_runtime.h>
#include <cuda_bf16.h>

#define SEQ   512
#define BATCH 2048
#define NTOK  (SEQ * BATCH)
#define VOCAB 50000
#define NBP   (BATCH / 2)            // batch pairs

typedef unsigned long long u64;

// scratch ( __device__ globals: allocation-free )
__device__ float g_M0[48 * 16];                  // fused wih0 @ w_e
__device__ float g_c0[48];                       // fused bias
__device__ float g_G0[(size_t)VOCAB * 64];       // [v][d*32 + j*4 + gate] (gate 3 = pad)
#define H0PAD ((size_t)4 * NBP * 16)             // u64 units, 4-step overrun pad each side
__device__ __align__(16) u64 g_h0p[H0PAD + (size_t)SEQ * NBP * 16 + H0PAD];
__device__ float g_h1[(size_t)NTOK * 16];        // layer1 output (normal [t][b][16])

// ---------------- packed f32x2 helpers ----------------
__device__ __forceinline__ u64 pk(float lo, float hi) {
    u64 r; asm("mov.b64 %0,{%1,%2};" : "=l"(r) : "f"(lo), "f"(hi)); return r;
}
__device__ __forceinline__ void upk(float& lo, float& hi, u64 v) {
    asm("mov.b64 {%0,%1},%2;" : "=f"(lo), "=f"(hi) : "l"(v));
}
__device__ __forceinline__ u64 ffma2(u64 a, u64 b, u64 c) {
    u64 r; asm("fma.rn.f32x2 %0,%1,%2,%3;" : "=l"(r) : "l"(a), "l"(b), "l"(c)); return r;
}
__device__ __forceinline__ u64 fadd2(u64 a, u64 b) {
    u64 r; asm("add.rn.f32x2 %0,%1,%2;" : "=l"(r) : "l"(a), "l"(b)); return r;
}
__device__ __forceinline__ u64 fmul2(u64 a, u64 b) {
    u64 r; asm("mul.rn.f32x2 %0,%1,%2;" : "=l"(r) : "l"(a), "l"(b)); return r;
}
__device__ __forceinline__ float tanhap(float x) {
    float y; asm("tanh.approx.f32 %0, %1;" : "=f"(y) : "f"(x)); return y;
}
__device__ __forceinline__ u64 tanh2(u64 v) {
    float lo, hi; upk(lo, hi, v); return pk(tanhap(lo), tanhap(hi));
}
__device__ __forceinline__ u64 sig2(u64 v, u64 HALF2) {
    return ffma2(tanh2(fmul2(v, HALF2)), HALF2, HALF2);
}
__device__ __forceinline__ u64 shfl2(u64 v, int k) {
    double d = __longlong_as_double((long long)v);
    d = __shfl_sync(0xffffffffu, d, k, 8);
    return (u64)__double_as_longlong(d);
}

// ---------------------------------------------------------------------------
// prep: M0[o][e] = sum_h wih0[o][h] * w_e[h][e] ; c0[o] = bih0[o] + wih0[o]·b_e
// ---------------------------------------------------------------------------
__global__ void prep_M0(const float* __restrict__ w_e, const float* __restrict__ b_e,
                        const float* __restrict__ wih, const float* __restrict__ bih) {
    int tid = threadIdx.x;
    if (tid < 768) {
        int o = tid >> 4, e = tid & 15;
        float acc = 0.0f;
#pragma unroll
        for (int h = 0; h < 16; h++) acc = fmaf(wih[o * 16 + h], w_e[h * 16 + e], acc);
        g_M0[o * 16 + e] = acc;
    }
    if (tid < 48) {
        float acc = bih[tid];
#pragma unroll
        for (int h = 0; h < 16; h++) acc = fmaf(wih[tid * 16 + h], b_e[h], acc);
        g_c0[tid] = acc;
    }
}

// G0[v][d*32 + j*4 + g] = table[v]·M0[d*24+g*8+j] + c0[...] (g==3 -> 0 pad)
__global__ void build_G0(const float* __restrict__ table) {
    int idx = blockIdx.x * blockDim.x + threadIdx.x;
    if (idx >= VOCAB * 64) return;
    int v = idx >> 6, o = idx & 63;
    int d = o >> 5, rem = o & 31, j = rem >> 2, g = rem & 3;
    float val = 0.0f;
    if (g < 3) {
        int row = d * 24 + g * 8 + j;
        const float* tr = table + (size_t)v * 16;
        const float* mr = g_M0 + row * 16;
        float acc = g_c0[row];
#pragma unroll
        for (int e = 0; e < 16; e++) acc = fmaf(tr[e], mr[e], acc);
        val = acc;
    }
    g_G0[idx] = val;
}

// ---------------------------------------------------------------------------
// scan0: layer-0 GRU, 2 batch elements per thread packed in f32x2.
// Group of 8 lanes handles batch pair bp (b = 2bp, 2bp+1); lane j owns h_j of
// both. Input gates gathered from G0 (1 LDG.128 per elem, prefetch depth 3,
// ids depth 6). Writes h0 in pair-interleaved layout [t][bp][col][2].
// ---------------------------------------------------------------------------
__global__ void __launch_bounds__(128) scan0_kernel(
        const int* __restrict__ x,
        const float* __restrict__ whh_all,
        const float* __restrict__ bhh_all) {
    const int d  = blockIdx.y;
    const int j  = threadIdx.x & 7;
    const int bp = blockIdx.x * 16 + (threadIdx.x >> 3);

    const float* whh = whh_all + d * 24 * 8;
    const float* bhh = bhh_all + d * 24;

    u64 whrp[8], whzp[8], whnp[8];
#pragma unroll
    for (int k = 0; k < 8; k++) {
        float a = whh[(0  + j) * 8 + k]; whrp[k] = pk(a, a);
        float b = whh[(8  + j) * 8 + k]; whzp[k] = pk(b, b);
        float c = whh[(16 + j) * 8 + k]; whnp[k] = pk(c, c);
    }
    const u64 brp = pk(bhh[j], bhh[j]);
    const u64 bzp = pk(bhh[8 + j], bhh[8 + j]);
    const u64 bnp = pk(bhh[16 + j], bhh[16 + j]);
    const u64 HALF2 = pk(0.5f, 0.5f);
    const u64 NEG1  = pk(-1.0f, -1.0f);
    const int go = d * 32 + j * 4;

    auto tmap = [&](int s) {
        int c = s < SEQ - 1 ? s : SEQ - 1;
        return d ? (SEQ - 1 - c) : c;
    };
    auto ld_ids = [&](int s) {
        return *reinterpret_cast<const int2*>(x + (size_t)tmap(s) * BATCH + 2 * bp);
    };
    auto g0row = [&](int v) {
        return *reinterpret_cast<const float4*>(g_G0 + (size_t)v * 64 + go);
    };

    int2 iw = ld_ids(0), ix = ld_ids(1), iy = ld_ids(2);
    float4 A0 = g0row(iw.x), B0 = g0row(iw.y);
    float4 A1 = g0row(ix.x), B1 = g0row(ix.y);
    float4 A2 = g0row(iy.x), B2 = g0row(iy.y);
    int2 i0 = ld_ids(3), i1 = ld_ids(4), i2 = ld_ids(5);

    u64 h = 0ull;                                  // {0.f, 0.f}
    for (int s = 0; s < SEQ; s++) {
        int2 inew = ld_ids(s + 6);
        float4 nA = g0row(i0.x), nB = g0row(i0.y); // gates for step s+3

        u64 gr = pk(A0.x, B0.x), gz = pk(A0.y, B0.y), gn = pk(A0.z, B0.z);

        u64 ghr = brp, ghz = bzp, ghn = bnp;
#pragma unroll
        for (int k = 0; k < 8; k++) {
            u64 hk = shfl2(h, k);
            ghr = ffma2(whrp[k], hk, ghr);
            ghz = ffma2(whzp[k], hk, ghz);
            ghn = ffma2(whnp[k], hk, ghn);
        }
        u64 r = sig2(fadd2(gr, ghr), HALF2);
        u64 z = sig2(fadd2(gz, ghz), HALF2);
        u64 n = tanh2(ffma2(r, ghn, gn));
        u64 hn = ffma2(n, NEG1, h);                // h - n
        h = ffma2(z, hn, n);

        int tt = d ? (SEQ - 1 - s) : s;
        g_h0p[H0PAD + ((size_t)tt * NBP + bp) * 16 + d * 8 + j] = h;

        A0 = A1; A1 = A2; A2 = nA;
        B0 = B1; B1 = B2; B2 = nB;
        i0 = i1; i1 = i2; i2 = inew;
    }
}

// ---------------------------------------------------------------------------
// scan1: layer-1 GRU, dual-batch packed, input-side matvec fused.
// Lane j loads cols {2j,2j+1} of the packed h0 pair-row (1 LDG.128, prefetch
// depth 3), broadcasts 64-bit pairs via shuffles, 48 FFMA2 input-side + 24
// FFMA2 hidden-side. Writes h1 in normal layout for the head.
// ---------------------------------------------------------------------------
__global__ void __launch_bounds__(128) scan1_kernel(
        const float* __restrict__ wih_all,
        const float* __restrict__ bih_all,
        const float* __restrict__ whh_all,
        const float* __restrict__ bhh_all) {
    const int d  = blockIdx.y;
    const int j  = threadIdx.x & 7;
    const int bp = blockIdx.x * 16 + (threadIdx.x >> 3);

    const float* wih = wih_all + (48 + d * 24) * 16;
    const float* bih = bih_all + 48 + d * 24;
    const float* whh = whh_all + (2 + d) * 24 * 8;
    const float* bhh = bhh_all + (2 + d) * 24;

    u64 airp[16], aizp[16], ainp[16];
#pragma unroll
    for (int k = 0; k < 16; k++) {
        float a = wih[(0  + j) * 16 + k]; airp[k] = pk(a, a);
        float b = wih[(8  + j) * 16 + k]; aizp[k] = pk(b, b);
        float c = wih[(16 + j) * 16 + k]; ainp[k] = pk(c, c);
    }
    u64 whrp[8], whzp[8], whnp[8];
#pragma unroll
    for (int k = 0; k < 8; k++) {
        float a = whh[(0  + j) * 8 + k]; whrp[k] = pk(a, a);
        float b = whh[(8  + j) * 8 + k]; whzp[k] = pk(b, b);
        float c = whh[(16 + j) * 8 + k]; whnp[k] = pk(c, c);
    }
    float brs = bih[j] + bhh[j];
    float bzs = bih[8 + j] + bhh[8 + j];
    const u64 brp  = pk(brs, brs);
    const u64 bzp  = pk(bzs, bzs);
    const u64 bnip = pk(bih[16 + j], bih[16 + j]);
    const u64 bnhp = pk(bhh[16 + j], bhh[16 + j]);
    const u64 HALF2 = pk(0.5f, 0.5f);
    const u64 NEG1  = pk(-1.0f, -1.0f);

    const int t0 = d ? (SEQ - 1) : 0;
    const int dt = d ? -1 : 1;
    const ptrdiff_t stp = (ptrdiff_t)dt * NBP * 8;          // ulonglong2 per t-step

    const ulonglong2* p = reinterpret_cast<const ulonglong2*>(g_h0p + H0PAD)
                        + ((size_t)t0 * NBP + bp) * 8 + j;  // cols 2j,2j+1 packed
    ulonglong2 X0 = p[0];
    ulonglong2 X1 = p[stp];
    ulonglong2 X2 = p[2 * stp];
    const ulonglong2* pf = p + 3 * stp;                     // runs into pad at tail

    u64 h = 0ull;
    int t = t0;
    for (int s = 0; s < SEQ; s++, t += dt) {
        ulonglong2 xn = *pf;
        pf += stp;

        // input-side gates (independent of h chain)
        u64 gr = brp, gz = bzp, gn = bnip;
#pragma unroll
        for (int k = 0; k < 8; k++) {
            u64 e0 = shfl2(X0.x, k);                        // col 2k   (pair)
            u64 e1 = shfl2(X0.y, k);                        // col 2k+1 (pair)
            gr = ffma2(airp[2 * k], e0, gr); gr = ffma2(airp[2 * k + 1], e1, gr);
            gz = ffma2(aizp[2 * k], e0, gz); gz = ffma2(aizp[2 * k + 1], e1, gz);
            gn = ffma2(ainp[2 * k], e0, gn); gn = ffma2(ainp[2 * k + 1], e1, gn);
        }

        // hidden-side gates (serial chain)
        u64 ghr = 0ull, ghz = 0ull, ghn = bnhp;
#pragma unroll
        for (int k = 0; k < 8; k++) {
            u64 hk = shfl2(h, k);
            ghr = ffma2(whrp[k], hk, ghr);
            ghz = ffma2(whzp[k], hk, ghz);
            ghn = ffma2(whnp[k], hk, ghn);
        }
        u64 r = sig2(fadd2(gr, ghr), HALF2);
        u64 z = sig2(fadd2(gz, ghz), HALF2);
        u64 n = tanh2(ffma2(r, ghn, gn));
        u64 hn = ffma2(n, NEG1, h);
        h = ffma2(z, hn, n);

        float hlo, hhi;
        upk(hlo, hhi, h);
        size_t base = ((size_t)t * BATCH + 2 * bp) * 16 + d * 8 + j;
        g_h1[base]      = hlo;
        g_h1[base + 16] = hhi;

        X0 = X1; X1 = X2; X2 = xn;
    }
}

// ---------------------------------------------------------------------------
// head: out = gelu(h1 @ w_g.T + b_g) @ w_o.T + b_o.  16 lanes/token,
// one coalesced load per lane + shuffle broadcast.
// ---------------------------------------------------------------------------
__global__ void __launch_bounds__(256) head_kernel(
        const float* __restrict__ w_g, const float* __restrict__ b_g,
        const float* __restrict__ w_o, const float* __restrict__ b_o,
        float* __restrict__ out) {
    int gtid = blockIdx.x * blockDim.x + threadIdx.x;
    int L = gtid & 15;
    int slot = gtid >> 4;
    int G = (gridDim.x * blockDim.x) >> 4;

    float wg[16];
#pragma unroll
    for (int k = 0; k < 16; k++) wg[k] = w_g[L * 16 + k];
    float bg = b_g[L];

    float wo[16];
    float bo = 0.0f;
    if (L < 10) {
#pragma unroll
        for (int k = 0; k < 16; k++) wo[k] = w_o[L * 16 + k];
        bo = b_o[L];
    } else {
#pragma unroll
        for (int k = 0; k < 16; k++) wo[k] = 0.0f;
    }

    for (int tok = slot; tok < NTOK; tok += G) {
        float hv = g_h1[(size_t)tok * 16 + L];
        float acc = bg;
#pragma unroll
        for (int k = 0; k < 16; k++)
            acc = fmaf(wg[k], __shfl_sync(0xffffffffu, hv, k, 16), acc);
        float y = acc * normcdff(acc);             // exact gelu
        float o = bo;
#pragma unroll
        for (int k = 0; k < 16; k++)
            o = fmaf(wo[k], __shfl_sync(0xffffffffu, y, k, 16), o);
        if (L < 10) out[(size_t)tok * 10 + L] = o;
    }
}

// ---------------------------------------------------------------------------
extern "C" void kernel_launch(void* const* d_in, const int* in_sizes, int n_in,
                              void* d_out, int out_size) {
    const int*   x     = (const int*)d_in[0];
    const float* table = (const float*)d_in[1];
    const float* w_e   = (const float*)d_in[2];
    const float* b_e   = (const float*)d_in[3];
    const float* wih   = (const float*)d_in[4];
    const float* whh   = (const float*)d_in[5];
    const float* bih   = (const float*)d_in[6];
    const float* bhh   = (const float*)d_in[7];
    const float* w_g   = (const float*)d_in[8];
    const float* b_g   = (const float*)d_in[9];
    const float* w_o   = (const float*)d_in[10];
    const float* b_o   = (const float*)d_in[11];
    float* out = (float*)d_out;

    prep_M0<<<1, 768>>>(w_e, b_e, wih, bih);
    build_G0<<<(VOCAB * 64 + 255) / 256, 256>>>(table);

    dim3 gs(BATCH / 32, 2);                        // 128 blocks of 128 thr
    scan0_kernel<<<gs, 128>>>(x, whh, bhh);
    scan1_kernel<<<gs, 128>>>(wih, bih, whh, bhh);
    head_kernel<<<2048, 256>>>(w_g, b_g, w_o, b_o, out);
}